// round 17
// baseline (speedup 1.0000x reference)
#include <cuda_runtime.h>
#include <cuda_bf16.h>
#include <cstdint>

// Chunked-parallel scan of:  s = sigmoid(10*(s + (Wx+b)_t - 0.5)),  pred_t = x_t . s
// Run in t = 2s-1 domain:  t' = tanh(2.5 t + 5(Wx+b)),
// pred = 0.5*(x.t) + 0.5*(x0+x1+x2).
//
// R17: packed f32x2 dual-chunk. Each lane runs TWO independent chunks (A = lane,
// B = lane+32 within the warp's 64-chunk span) with all FMA work packed into
// fma.rn.f32x2 (one instruction does both chunks). ~30-45% fewer issued
// instructions than R11 for the same FLOPs; tanh stays scalar MUFU (6 chains).
// Memory design = R11's proven flat window extended to 64 chunks: one
// contiguous 1548-f4 span per warp, slot = span*25 + w (conflict-free at lane
// stride 25), one-shot cp.async in 2 commit groups (G0 warmup halves /
// G1 main halves) with progressive drain; preds stashed in consumed slots,
// stored fully coalesced. Warp-local sync only.

static constexpr int CHUNK  = 32;               // steps per chunk (24 f4)
static constexpr int WM     = 16;               // warmup steps (12 f4)
static constexpr int TPB    = 64;               // 2 warps per block
static constexpr int WPB    = TPB / 32;
static constexpr int G0N    = 65 * 12;          // 780 f4 (w in [0,12), spans 0..64)
static constexpr int G1N    = 64 * 12;          // 768 f4 (w in [12,24), spans 0..63)
static constexpr int WSLICE = 1612;             // max slot 64*25+11 = 1611, +1
static constexpr int SMEM_BYTES = WPB * WSLICE * 16;   // 51584 B

__device__ __forceinline__ float tanhapx(float z) {
    float r; asm("tanh.approx.f32 %0, %1;" : "=f"(r) : "f"(z)); return r;
}
__device__ __forceinline__ void cp16(unsigned int dst, const void* src) {
    asm volatile("cp.async.cg.shared.global [%0], [%1], 16;" :: "r"(dst), "l"(src));
}
__device__ __forceinline__ unsigned long long pk(float lo, float hi) {
    unsigned long long r;
    asm("mov.b64 %0, {%1, %2};" : "=l"(r) : "f"(lo), "f"(hi));
    return r;
}
__device__ __forceinline__ void upk(float& lo, float& hi, unsigned long long v) {
    asm("mov.b64 {%0, %1}, %2;" : "=f"(lo), "=f"(hi) : "l"(v));
}
__device__ __forceinline__ unsigned long long ffma2(unsigned long long a,
                                                    unsigned long long b,
                                                    unsigned long long c) {
    unsigned long long d;
    asm("fma.rn.f32x2 %0, %1, %2, %3;" : "=l"(d) : "l"(a), "l"(b), "l"(c));
    return d;
}

__global__ void __launch_bounds__(TPB, 4)
updater_kernel(const float* __restrict__ x,
               const float* __restrict__ Wg,
               const float* __restrict__ bg,
               const float* __restrict__ net0,
               float* __restrict__ out)
{
    extern __shared__ float4 sm[];

    const int lane = threadIdx.x & 31;
    const int wid  = threadIdx.x >> 5;
    const int w0c  = blockIdx.x * 128 + wid * 64;       // warp's first chunk (of 64)
    const bool first = (blockIdx.x == 0) && (wid == 0) && (lane == 0);

    // packed constants: u5 = 5*(W x + b)
    const unsigned long long W00p = pk(5.f*Wg[0], 5.f*Wg[0]);
    const unsigned long long W01p = pk(5.f*Wg[1], 5.f*Wg[1]);
    const unsigned long long W02p = pk(5.f*Wg[2], 5.f*Wg[2]);
    const unsigned long long W10p = pk(5.f*Wg[3], 5.f*Wg[3]);
    const unsigned long long W11p = pk(5.f*Wg[4], 5.f*Wg[4]);
    const unsigned long long W12p = pk(5.f*Wg[5], 5.f*Wg[5]);
    const unsigned long long W20p = pk(5.f*Wg[6], 5.f*Wg[6]);
    const unsigned long long W21p = pk(5.f*Wg[7], 5.f*Wg[7]);
    const unsigned long long W22p = pk(5.f*Wg[8], 5.f*Wg[8]);
    const unsigned long long c0p  = pk(5.f*bg[0], 5.f*bg[0]);
    const unsigned long long c1p  = pk(5.f*bg[1], 5.f*bg[1]);
    const unsigned long long c2p  = pk(5.f*bg[2], 5.f*bg[2]);
    const unsigned long long k25p = pk(2.5f, 2.5f);
    const unsigned long long hfp  = pk(0.5f, 0.5f);
    const unsigned long long zp   = pk(0.f, 0.f);

    const float4* __restrict__ xf4 = reinterpret_cast<const float4*>(x);
    float4* __restrict__ of4 = reinterpret_cast<float4*>(out);

    float4* xw = sm + wid * WSLICE;
    const unsigned int sbase = (unsigned int)__cvta_generic_to_shared(xw);
    const long gbase = (long)w0c * 24 - 12;             // span start (global f4)

    // ---- G0: warmup halves, w in [0,12), spans 0..64 (780 f4) ----
    #pragma unroll
    for (int l = 0; l < 25; ++l) {
        int i = lane + 32 * l;                  // 0..799
        if (i < G0N) {
            int span = i / 12, w = i - span * 12;
            long g = gbase + span * 24 + w;
            if (g < 0) g = 0;                   // only global chunk 0's discarded warmup
            cp16(sbase + (unsigned int)(span * 25 + w) * 16u, xf4 + g);
        }
    }
    asm volatile("cp.async.commit_group;");

    // ---- G1: main halves, w in [12,24), spans 0..63 (768 f4) ----
    #pragma unroll
    for (int l = 0; l < 24; ++l) {
        int i = lane + 32 * l;                  // 0..767, bijective
        int span = i / 12, w = i - span * 12;
        long g = gbase + span * 24 + 12 + w;    // >= 0 always
        cp16(sbase + (unsigned int)(span * 25 + 12 + w) * 16u, xf4 + g);
    }
    asm volatile("cp.async.commit_group;");

    // packed state (A = chunk w0c+lane, B = chunk w0c+lane+32); seed s=0.5 -> t=0
    unsigned long long T0 = zp, T1 = zp, T2 = zp;

    float4* myA = xw + lane * 25;               // A span base
    float4* myB = myA + 32 * 25;                // B span base (+800 f4)

    // one packed recurrence step; returns packed (predA, predB)
    auto pstep = [&](const float4& a, const float4& b, int c) -> unsigned long long {
        float A0, A1, A2, B0, B1, B2;
        if (c == 0)      { A0 = a.x; A1 = a.y; A2 = a.z; B0 = b.x; B1 = b.y; B2 = b.z; }
        else if (c == 1) { A0 = a.w; A1 = a.x; A2 = a.y; B0 = b.w; B1 = b.x; B2 = b.y; }
        else if (c == 2) { A0 = a.z; A1 = a.w; A2 = a.x; B0 = b.z; B1 = b.w; B2 = b.x; }
        else             { A0 = a.y; A1 = a.z; A2 = a.w; B0 = b.y; B1 = b.z; B2 = b.w; }
        unsigned long long x0 = pk(A0, B0), x1 = pk(A1, B1), x2 = pk(A2, B2);
        unsigned long long u0 = ffma2(W00p, x0, ffma2(W01p, x1, ffma2(W02p, x2, c0p)));
        unsigned long long u1 = ffma2(W10p, x0, ffma2(W11p, x1, ffma2(W12p, x2, c1p)));
        unsigned long long u2 = ffma2(W20p, x0, ffma2(W21p, x1, ffma2(W22p, x2, c2p)));
        unsigned long long z0 = ffma2(k25p, T0, u0);
        unsigned long long z1 = ffma2(k25p, T1, u1);
        unsigned long long z2 = ffma2(k25p, T2, u2);
        float la, ha, lb, hb, lc, hc;
        upk(la, ha, z0); upk(lb, hb, z1); upk(lc, hc, z2);
        T0 = pk(tanhapx(la), tanhapx(ha));
        T1 = pk(tanhapx(lb), tanhapx(hb));
        T2 = pk(tanhapx(lc), tanhapx(hc));
        unsigned long long h = ffma2(hfp, x2, ffma2(hfp, x1, ffma2(hfp, x0, zp)));
        unsigned long long d = ffma2(x0, T0, ffma2(x1, T1, ffma2(x2, T2, zp)));
        return ffma2(hfp, d, h);
    };

    // ---- warmup: 16 steps, j = 0..11 of both spans (G0) ----
    asm volatile("cp.async.wait_group 1;");
    __syncwarp();
    #pragma unroll
    for (int g = 0; g < WM / 4; ++g) {
        float4 pA = myA[3*g], qA = myA[3*g+1], rA = myA[3*g+2];
        float4 pB = myB[3*g], qB = myB[3*g+1], rB = myB[3*g+2];
        pstep(pA, pB, 0);
        { float4 a = make_float4(pA.w, qA.x, qA.y, 0.f), b = make_float4(pB.w, qB.x, qB.y, 0.f);
          pstep(a, b, 0); }
        { float4 a = make_float4(qA.z, qA.w, rA.x, 0.f), b = make_float4(qB.z, qB.w, rB.x, 0.f);
          pstep(a, b, 0); }
        { float4 a = make_float4(rA.y, rA.z, rA.w, 0.f), b = make_float4(rB.y, rB.z, rB.w, 0.f);
          pstep(a, b, 0); }
    }
    if (first) {                                // override A half (global chunk 0)
        float lo, hi;
        upk(lo, hi, T0); T0 = pk(fmaf(2.f, net0[0], -1.f), hi);
        upk(lo, hi, T1); T1 = pk(fmaf(2.f, net0[1], -1.f), hi);
        upk(lo, hi, T2); T2 = pk(fmaf(2.f, net0[2], -1.f), hi);
    }

    // ---- main: 32 steps, j = 12..35 (j>=24 -> next span's G0 slots, +1 bump) ----
    asm volatile("cp.async.wait_group 0;");
    __syncwarp();

    #pragma unroll
    for (int g = 0; g < 8; ++g) {
        int j0 = 12 + 3*g, j1 = 13 + 3*g, j2 = 14 + 3*g;
        float4 pA = myA[j0 + (j0 >= 24 ? 1 : 0)];
        float4 qA = myA[j1 + (j1 >= 24 ? 1 : 0)];
        float4 rA = myA[j2 + (j2 >= 24 ? 1 : 0)];
        float4 pB = myB[j0 + (j0 >= 24 ? 1 : 0)];
        float4 qB = myB[j1 + (j1 >= 24 ? 1 : 0)];
        float4 rB = myB[j2 + (j2 >= 24 ? 1 : 0)];
        unsigned long long r0 = pstep(pA, pB, 0);
        unsigned long long r1, r2, r3;
        { float4 a = make_float4(pA.w, qA.x, qA.y, 0.f), b = make_float4(pB.w, qB.x, qB.y, 0.f);
          r1 = pstep(a, b, 0); }
        { float4 a = make_float4(qA.z, qA.w, rA.x, 0.f), b = make_float4(qB.z, qB.w, rB.x, 0.f);
          r2 = pstep(a, b, 0); }
        { float4 a = make_float4(rA.y, rA.z, rA.w, 0.f), b = make_float4(rB.y, rB.z, rB.w, 0.f);
          r3 = pstep(a, b, 0); }
        float4 resA, resB;
        upk(resA.x, resB.x, r0);
        upk(resA.y, resB.y, r1);
        upk(resA.z, resB.z, r2);
        upk(resA.w, resB.w, r3);
        myA[12 + g] = resA;                     // consumed own-span G1 slots
        myB[12 + g] = resB;
    }
    __syncwarp();

    // ---- coalesced store: 64 chunks x 8 pred f4 per warp ----
    #pragma unroll
    for (int l = 0; l < 16; ++l) {
        int i = lane + 32 * l;                  // 0..511
        int seg = i >> 3, off = i & 7;
        of4[(long)(w0c + seg) * 8 + off] = xw[seg * 25 + 12 + off];
    }
}

extern "C" void kernel_launch(void* const* d_in, const int* in_sizes, int n_in,
                              void* d_out, int out_size)
{
    const float* x    = (const float*)d_in[0];
    const float* W    = (const float*)d_in[1];
    const float* b    = (const float*)d_in[2];
    const float* net0 = (const float*)d_in[3];
    float* out = (float*)d_out;

    cudaFuncSetAttribute(updater_kernel,
                         cudaFuncAttributeMaxDynamicSharedMemorySize, SMEM_BYTES);

    int n       = in_sizes[0] / 3;     // B = 4194304
    int nchunks = n / CHUNK;           // 131072
    int blocks  = nchunks / 128;       // 1024 (2 warps x 64 chunks per block)
    updater_kernel<<<blocks, TPB, SMEM_BYTES>>>(x, W, b, net0, out);
}